// round 1
// baseline (speedup 1.0000x reference)
#include <cuda_runtime.h>
#include <math.h>

// ---- problem constants ----
#define B_    4
#define NTOT  400
#define N1    256     // source-1 windows (16x16)
#define N2    144     // source-2 windows (12x12)
#define DIM   256
#define NH    8
#define PIX   64      // 8x8 window
// head dims: DH=32 (INNER/NH), DCH=8, DV=2048
// pixels per batch: 25600 (16384 src1 + 9216 src2); total M = 102400

// ---- scratch (no cudaMalloc allowed) ----
__device__ float g_fqk[B_ * NTOT * 512];            // rms'd: [q(256) | k(256)]
__device__ float g_cqk[B_ * NTOT * 128];            // rms'd: [cq(64) | ck(64)]
__device__ float g_attn[B_ * NH * NTOT * 256];      // compact: row n -> cols over opposite segment
__device__ float g_values[26214400];                // (b, w, p, 256)
__device__ float g_vout[26214400];                  // (b, w, p, 256)

// map flat pixel row m = ((b*400 + w)*64 + p) -> source pixel pointer
__device__ __forceinline__ const float* pixel_ptr(const float* __restrict__ x1,
                                                  const float* __restrict__ x2, int m) {
    int b = m / 25600;
    int r = m % 25600;
    int w = r >> 6;
    int p = r & 63;
    int py = p >> 3, px = p & 7;
    if (w < N1) {
        int y = (w >> 4) * 8 + py, xx = (w & 15) * 8 + px;
        return x1 + ((size_t)((b * 128 + y) * 128 + xx)) * DIM;
    } else {
        int w2 = w - N1;
        int y = (w2 / 12) * 8 + py, xx = (w2 % 12) * 8 + px;
        return x2 + ((size_t)((b * 96 + y) * 96 + xx)) * DIM;
    }
}

__device__ __forceinline__ float* out_pixel_ptr(float* __restrict__ out, int m) {
    int b = m / 25600;
    int r = m % 25600;
    int w = r >> 6;
    int p = r & 63;
    int py = p >> 3, px = p & 7;
    if (w < N1) {
        int y = (w >> 4) * 8 + py, xx = (w & 15) * 8 + px;
        return out + ((size_t)((b * 128 + y) * 128 + xx)) * DIM;
    } else {
        int w2 = w - N1;
        int y = (w2 / 12) * 8 + py, xx = (w2 % 12) * 8 + px;
        return out + 16777216 + ((size_t)((b * 96 + y) * 96 + xx)) * DIM;
    }
}

// ============================================================================
// K1: per-window mean of x and c, then QK projections + RMS norm
// grid: (B_*NTOT) blocks, 512 threads
// ============================================================================
__global__ __launch_bounds__(512) void k_embed(
    const float* __restrict__ x1, const float* __restrict__ c1,
    const float* __restrict__ x2, const float* __restrict__ c2,
    const float* __restrict__ fqk_w, const float* __restrict__ fqk_b, const float* __restrict__ fqk_g,
    const float* __restrict__ cqk_w, const float* __restrict__ cqk_b, const float* __restrict__ cqk_g)
{
    int bw = blockIdx.x;
    int b = bw / NTOT, w = bw % NTOT;
    __shared__ __align__(16) float favg[256];
    __shared__ float cavg[4];
    __shared__ float redf[16];
    __shared__ float redc[4];
    int t = threadIdx.x;

    const float* xbase;
    const float* cbase;
    int rowstride, crowstride;
    if (w < N1) {
        int wy = w >> 4, wx = w & 15;
        xbase = x1 + ((size_t)((b * 128 + wy * 8) * 128 + wx * 8)) * DIM;
        cbase = c1 + ((size_t)((b * 128 + wy * 8) * 128 + wx * 8)) * 4;
        rowstride = 128 * DIM; crowstride = 128 * 4;
    } else {
        int w2 = w - N1;
        int wy = w2 / 12, wx = w2 % 12;
        xbase = x2 + ((size_t)((b * 96 + wy * 8) * 96 + wx * 8)) * DIM;
        cbase = c2 + ((size_t)((b * 96 + wy * 8) * 96 + wx * 8)) * 4;
        rowstride = 96 * DIM; crowstride = 96 * 4;
    }

    if (t < 256) {
        float s = 0.f;
        #pragma unroll
        for (int py = 0; py < 8; ++py)
            #pragma unroll
            for (int px = 0; px < 8; ++px)
                s += xbase[py * rowstride + px * DIM + t];
        favg[t] = s * (1.f / 64.f);
    } else if (t < 260) {
        int ch = t - 256;
        float s = 0.f;
        for (int py = 0; py < 8; ++py)
            for (int px = 0; px < 8; ++px)
                s += cbase[py * crowstride + px * 4 + ch];
        cavg[ch] = s * (1.f / 64.f);
    }
    __syncthreads();

    // f projection: output o = t (0..511), dot over 256
    const float4* fw = (const float4*)(fqk_w + (size_t)t * 256);
    const float4* fa = (const float4*)favg;
    float rawf = fqk_b[t];
    #pragma unroll 8
    for (int d4 = 0; d4 < 64; ++d4) {
        float4 wv = fw[d4];
        float4 av = fa[d4];
        rawf += wv.x * av.x + wv.y * av.y + wv.z * av.z + wv.w * av.w;
    }
    float rawc = 0.f;
    if (t < 128) {
        rawc = cqk_b[t] + cavg[0] * cqk_w[t * 4 + 0] + cavg[1] * cqk_w[t * 4 + 1]
             + cavg[2] * cqk_w[t * 4 + 2] + cavg[3] * cqk_w[t * 4 + 3];
    }

    // RMS over the full 512 (f) and 128 (c) vectors
    float sf = rawf * rawf;
    #pragma unroll
    for (int o = 16; o; o >>= 1) sf += __shfl_xor_sync(~0u, sf, o);
    if ((t & 31) == 0) redf[t >> 5] = sf;
    if (t < 128) {
        float sc2 = rawc * rawc;
        #pragma unroll
        for (int o = 16; o; o >>= 1) sc2 += __shfl_xor_sync(~0u, sc2, o);
        if ((t & 31) == 0) redc[t >> 5] = sc2;
    }
    __syncthreads();
    float msf = 0.f;
    #pragma unroll
    for (int i = 0; i < 16; ++i) msf += redf[i];
    float invf = rsqrtf(msf * (1.f / 512.f) + 1e-6f);
    g_fqk[((size_t)(b * NTOT + w)) * 512 + t] = rawf * invf * fqk_g[t];
    if (t < 128) {
        float msc = redc[0] + redc[1] + redc[2] + redc[3];
        float invc = rsqrtf(msc * (1.f / 128.f) + 1e-6f);
        g_cqk[((size_t)(b * NTOT + w)) * 128 + t] = rawc * invc * cqk_g[t];
    }
}

// ============================================================================
// K2: V projection GEMM. C[m,o] = sum_d A[m,d] * v_w[o,d]
// M=102400 (gathered windowed pixels), N=256, K=256
// 128x128x8 tiles, 256 threads, 8x8 microtile, double-buffered smem
// grid: (2, 800)
// ============================================================================
__global__ __launch_bounds__(256) void k_vproj(
    const float* __restrict__ x1, const float* __restrict__ x2,
    const float* __restrict__ vw)
{
    __shared__ __align__(16) float As[2][8][128];
    __shared__ __align__(16) float Bs[2][8][128];
    int tid = threadIdx.x;
    int m0 = blockIdx.y * 128;
    int n0 = blockIdx.x * 128;

    int lrow = tid & 127;
    int lkh  = (tid >> 7) * 4;
    const float* aptr = pixel_ptr(x1, x2, m0 + lrow) + lkh;
    const float* bptr = vw + (size_t)(n0 + lrow) * 256 + lkh;

    float4 av = *(const float4*)aptr;
    float4 bv = *(const float4*)bptr;
    #pragma unroll
    for (int i = 0; i < 4; ++i) {
        As[0][lkh + i][lrow] = ((float*)&av)[i];
        Bs[0][lkh + i][lrow] = ((float*)&bv)[i];
    }
    __syncthreads();

    float acc[8][8];
    #pragma unroll
    for (int i = 0; i < 8; ++i)
        #pragma unroll
        for (int j = 0; j < 8; ++j) acc[i][j] = 0.f;

    int tx4 = (tid & 15) * 4;
    int ty4 = (tid >> 4) * 4;

    for (int kt = 0; kt < 32; ++kt) {
        int cur = kt & 1;
        if (kt < 31) {
            av = *(const float4*)(aptr + (kt + 1) * 8);
            bv = *(const float4*)(bptr + (kt + 1) * 8);
        }
        #pragma unroll
        for (int k = 0; k < 8; ++k) {
            float4 a0 = *(const float4*)&As[cur][k][ty4];
            float4 a1 = *(const float4*)&As[cur][k][64 + ty4];
            float4 b0 = *(const float4*)&Bs[cur][k][tx4];
            float4 b1 = *(const float4*)&Bs[cur][k][64 + tx4];
            float a[8] = {a0.x, a0.y, a0.z, a0.w, a1.x, a1.y, a1.z, a1.w};
            float bb[8] = {b0.x, b0.y, b0.z, b0.w, b1.x, b1.y, b1.z, b1.w};
            #pragma unroll
            for (int i = 0; i < 8; ++i)
                #pragma unroll
                for (int j = 0; j < 8; ++j) acc[i][j] += a[i] * bb[j];
        }
        if (kt < 31) {
            int nxt = cur ^ 1;
            #pragma unroll
            for (int i = 0; i < 4; ++i) {
                As[nxt][lkh + i][lrow] = ((float*)&av)[i];
                Bs[nxt][lkh + i][lrow] = ((float*)&bv)[i];
            }
        }
        __syncthreads();
    }

    #pragma unroll
    for (int i = 0; i < 8; ++i) {
        int row = (i < 4) ? (ty4 + i) : (64 + ty4 + (i - 4));
        float* c = g_values + (size_t)(m0 + row) * 256 + n0;
        *(float4*)(c + tx4)      = make_float4(acc[i][0], acc[i][1], acc[i][2], acc[i][3]);
        *(float4*)(c + 64 + tx4) = make_float4(acc[i][4], acc[i][5], acc[i][6], acc[i][7]);
    }
}

// ============================================================================
// K3: scores + softmax (cross-source mask exploited). One block per (n, b*8+h).
// Writes compact attn row: cols index opposite segment. 128 threads.
// ============================================================================
__global__ __launch_bounds__(128) void k_attn()
{
    int n  = blockIdx.x;
    int bh = blockIdx.y;
    int b = bh >> 3, h = bh & 7;
    int seg1 = (n >= N1);
    int colstart = seg1 ? 0 : N1;
    int cnt = seg1 ? N1 : N2;
    __shared__ float sc[256];
    __shared__ float red[4];
    int t = threadIdx.x;

    const float* qp  = g_fqk + ((size_t)(b * NTOT + n)) * 512 + h * 32;
    const float* cqp = g_cqk + ((size_t)(b * NTOT + n)) * 128 + h * 8;
    float fq[32], cq[8];
    #pragma unroll
    for (int i = 0; i < 32; ++i) fq[i] = qp[i];
    #pragma unroll
    for (int i = 0; i < 8; ++i) cq[i] = cqp[i];

    for (int m = t; m < cnt; m += 128) {
        int mg = colstart + m;
        const float* kp  = g_fqk + ((size_t)(b * NTOT + mg)) * 512 + 256 + h * 32;
        const float* ckp = g_cqk + ((size_t)(b * NTOT + mg)) * 128 + 64 + h * 8;
        float s = 0.f;
        #pragma unroll
        for (int i = 0; i < 32; ++i) s += fq[i] * kp[i];
        float s2 = 0.f;
        #pragma unroll
        for (int i = 0; i < 8; ++i) s2 += cq[i] * ckp[i];
        sc[m] = s * 0.1767766952966369f + s2 * 0.3535533905932738f;
    }
    __syncthreads();

    float mx = -1e30f;
    for (int m = t; m < cnt; m += 128) mx = fmaxf(mx, sc[m]);
    #pragma unroll
    for (int o = 16; o; o >>= 1) mx = fmaxf(mx, __shfl_xor_sync(~0u, mx, o));
    if ((t & 31) == 0) red[t >> 5] = mx;
    __syncthreads();
    mx = fmaxf(fmaxf(red[0], red[1]), fmaxf(red[2], red[3]));
    __syncthreads();

    float sum = 0.f;
    for (int m = t; m < cnt; m += 128) {
        float e = __expf(sc[m] - mx);
        sc[m] = e;
        sum += e;
    }
    #pragma unroll
    for (int o = 16; o; o >>= 1) sum += __shfl_xor_sync(~0u, sum, o);
    if ((t & 31) == 0) red[t >> 5] = sum;
    __syncthreads();
    sum = red[0] + red[1] + red[2] + red[3];
    float inv = 1.f / sum;
    float* dst = g_attn + ((size_t)(bh * NTOT + n)) * 256;
    for (int m = t; m < cnt; m += 128) dst[m] = sc[m] * inv;
}

// ============================================================================
// K4: v_out = attn @ vh per (b, h). Tiles 64x128, K extent 144/256.
// grid: (2048/128=16, ceil(400/64)=7, 32), 256 threads, 8x4 microtile
// ============================================================================
__global__ __launch_bounds__(256) void k_attnv()
{
    int bh = blockIdx.z;
    int b = bh >> 3, h = bh & 7;
    int n0 = blockIdx.y * 64;
    int j0 = blockIdx.x * 128;
    int seg1 = (n0 >= N1);
    int colstart = seg1 ? 0 : N1;
    int kExt = seg1 ? N1 : N2;
    __shared__ __align__(16) float As[2][8][64];
    __shared__ __align__(16) float Bs[2][8][128];
    int tid = threadIdx.x;

    int arow = tid & 63;
    int akh  = (tid >> 6) * 2;
    bool avalid = (n0 + arow) < NTOT;
    int asafe = avalid ? (n0 + arow) : (NTOT - 1);
    const float* aptr = g_attn + ((size_t)(bh * NTOT + asafe)) * 256 + akh;

    int bkrow = tid >> 5;
    int bjh   = (tid & 31) * 4;
    const float* bptr = g_values + ((size_t)(b * NTOT + colstart + bkrow)) * 16384
                      + h * 2048 + j0 + bjh;

    int nk = kExt >> 3;  // 18 or 32
    float2 a2 = avalid ? *(const float2*)aptr : make_float2(0.f, 0.f);
    float4 b4 = *(const float4*)bptr;
    As[0][akh][arow] = a2.x; As[0][akh + 1][arow] = a2.y;
    *(float4*)&Bs[0][bkrow][bjh] = b4;
    __syncthreads();

    float acc[8][4];
    #pragma unroll
    for (int i = 0; i < 8; ++i)
        #pragma unroll
        for (int j = 0; j < 4; ++j) acc[i][j] = 0.f;

    int ry = tid >> 5;   // row group: rows ry*8..+7
    int cx = tid & 31;   // col group: cols cx*4..+3

    for (int kt = 0; kt < nk; ++kt) {
        int cur = kt & 1;
        if (kt + 1 < nk) {
            a2 = avalid ? *(const float2*)(aptr + (kt + 1) * 8) : make_float2(0.f, 0.f);
            b4 = *(const float4*)(bptr + (size_t)(kt + 1) * 8 * 16384);
        }
        #pragma unroll
        for (int k = 0; k < 8; ++k) {
            float4 av0 = *(const float4*)&As[cur][k][ry * 8];
            float4 av1 = *(const float4*)&As[cur][k][ry * 8 + 4];
            float4 bv  = *(const float4*)&Bs[cur][k][cx * 4];
            float a[8] = {av0.x, av0.y, av0.z, av0.w, av1.x, av1.y, av1.z, av1.w};
            #pragma unroll
            for (int i = 0; i < 8; ++i) {
                acc[i][0] += a[i] * bv.x;
                acc[i][1] += a[i] * bv.y;
                acc[i][2] += a[i] * bv.z;
                acc[i][3] += a[i] * bv.w;
            }
        }
        if (kt + 1 < nk) {
            int nxt = cur ^ 1;
            As[nxt][akh][arow] = a2.x; As[nxt][akh + 1][arow] = a2.y;
            *(float4*)&Bs[nxt][bkrow][bjh] = b4;
        }
        __syncthreads();
    }

    #pragma unroll
    for (int i = 0; i < 8; ++i) {
        int n = n0 + ry * 8 + i;
        if (n < NTOT) {
            float* dst = g_vout + ((size_t)(b * NTOT + n)) * 16384 + h * 2048 + j0 + cx * 4;
            *(float4*)dst = make_float4(acc[i][0], acc[i][1], acc[i][2], acc[i][3]);
        }
    }
}

// ============================================================================
// K5: output projection GEMM + unwindow scatter.
// C[m,d] = sum_o v_out[m,o] * vb_w[d,o]; scatter rows to out1/out2 layout.
// Same tiling as k_vproj. grid: (2, 800)
// ============================================================================
__global__ __launch_bounds__(256) void k_outproj(
    const float* __restrict__ vbw, float* __restrict__ out)
{
    __shared__ __align__(16) float As[2][8][128];
    __shared__ __align__(16) float Bs[2][8][128];
    int tid = threadIdx.x;
    int m0 = blockIdx.y * 128;
    int n0 = blockIdx.x * 128;

    int lrow = tid & 127;
    int lkh  = (tid >> 7) * 4;
    const float* aptr = g_vout + (size_t)(m0 + lrow) * 256 + lkh;
    const float* bptr = vbw + (size_t)(n0 + lrow) * 256 + lkh;

    float4 av = *(const float4*)aptr;
    float4 bv = *(const float4*)bptr;
    #pragma unroll
    for (int i = 0; i < 4; ++i) {
        As[0][lkh + i][lrow] = ((float*)&av)[i];
        Bs[0][lkh + i][lrow] = ((float*)&bv)[i];
    }
    __syncthreads();

    float acc[8][8];
    #pragma unroll
    for (int i = 0; i < 8; ++i)
        #pragma unroll
        for (int j = 0; j < 8; ++j) acc[i][j] = 0.f;

    int tx4 = (tid & 15) * 4;
    int ty4 = (tid >> 4) * 4;

    for (int kt = 0; kt < 32; ++kt) {
        int cur = kt & 1;
        if (kt < 31) {
            av = *(const float4*)(aptr + (kt + 1) * 8);
            bv = *(const float4*)(bptr + (kt + 1) * 8);
        }
        #pragma unroll
        for (int k = 0; k < 8; ++k) {
            float4 a0 = *(const float4*)&As[cur][k][ty4];
            float4 a1 = *(const float4*)&As[cur][k][64 + ty4];
            float4 b0 = *(const float4*)&Bs[cur][k][tx4];
            float4 b1 = *(const float4*)&Bs[cur][k][64 + tx4];
            float a[8] = {a0.x, a0.y, a0.z, a0.w, a1.x, a1.y, a1.z, a1.w};
            float bb[8] = {b0.x, b0.y, b0.z, b0.w, b1.x, b1.y, b1.z, b1.w};
            #pragma unroll
            for (int i = 0; i < 8; ++i)
                #pragma unroll
                for (int j = 0; j < 8; ++j) acc[i][j] += a[i] * bb[j];
        }
        if (kt < 31) {
            int nxt = cur ^ 1;
            #pragma unroll
            for (int i = 0; i < 4; ++i) {
                As[nxt][lkh + i][lrow] = ((float*)&av)[i];
                Bs[nxt][lkh + i][lrow] = ((float*)&bv)[i];
            }
        }
        __syncthreads();
    }

    #pragma unroll
    for (int i = 0; i < 8; ++i) {
        int row = (i < 4) ? (ty4 + i) : (64 + ty4 + (i - 4));
        float* c = out_pixel_ptr(out, m0 + row) + n0;
        *(float4*)(c + tx4)      = make_float4(acc[i][0], acc[i][1], acc[i][2], acc[i][3]);
        *(float4*)(c + 64 + tx4) = make_float4(acc[i][4], acc[i][5], acc[i][6], acc[i][7]);
    }
}

// ============================================================================
extern "C" void kernel_launch(void* const* d_in, const int* in_sizes, int n_in,
                              void* d_out, int out_size)
{
    const float* x1    = (const float*)d_in[0];
    const float* c1    = (const float*)d_in[1];
    const float* x2    = (const float*)d_in[2];
    const float* c2    = (const float*)d_in[3];
    const float* fqk_w = (const float*)d_in[4];
    const float* fqk_b = (const float*)d_in[5];
    const float* fqk_g = (const float*)d_in[6];
    const float* cqk_w = (const float*)d_in[7];
    const float* cqk_b = (const float*)d_in[8];
    const float* cqk_g = (const float*)d_in[9];
    const float* v_w   = (const float*)d_in[10];
    const float* vb_w  = (const float*)d_in[11];
    float* out = (float*)d_out;

    k_embed<<<B_ * NTOT, 512>>>(x1, c1, x2, c2, fqk_w, fqk_b, fqk_g, cqk_w, cqk_b, cqk_g);
    k_vproj<<<dim3(2, 800), 256>>>(x1, x2, v_w);
    k_attn<<<dim3(NTOT, B_ * NH), 128>>>();
    k_attnv<<<dim3(16, 7, 32), 256>>>();
    k_outproj<<<dim3(2, 800), 256>>>(vb_w, out);
}